// round 11
// baseline (speedup 1.0000x reference)
#include <cuda_runtime.h>
#include <cstdint>

#define BATCH 4
#define SEQ   1024
#define EMB   768
#define HEADS 12
#define HDIM  64
#define BH    (BATCH*HEADS)    // 48
#define NSPL  6                // scan row-chunk replicas
#define NBLK  288              // 48 segments * 6 chunks

#define RS_ONE   (BH * HEADS * EMB)      // 442368 floats per replica
#define G_ELEMS  (BATCH * EMB)
#define G_OFF    (NSPL * RS_ONE)

__device__ float g_Acc[NSPL * RS_ONE + G_ELEMS];
__device__ unsigned g_barCnt = 0;
__device__ unsigned g_barGen = 0;   // monotonic across graph replays

__device__ __forceinline__ void grid_barrier()
{
    __threadfence();                 // every thread publishes its writes
    __syncthreads();
    if (threadIdx.x == 0) {
        const unsigned gen = *(volatile unsigned*)&g_barGen;
        unsigned t = atomicAdd(&g_barCnt, 1u);
        if (t == NBLK - 1) {
            atomicExch(&g_barCnt, 0u);
            __threadfence();
            atomicAdd(&g_barGen, 1u);            // release
        } else {
            while (*(volatile unsigned*)&g_barGen == gen) __nanosleep(64);
        }
    }
    __syncthreads();
    __threadfence();
}

__global__ void __launch_bounds__(192) fused_kernel(
    const float* __restrict__ value, const float* __restrict__ Wv,
    float* __restrict__ out)
{
    const int x   = blockIdx.x;
    const int tid = threadIdx.x;

    __shared__ float As_t[64][52];   // [k][bh], 52*4=208B row (16B aligned)
    __shared__ float Ws_t[64][68];   // [k][d],  68*4=272B row (16B aligned)

    // ============================ PHASE 1: scan ============================
    {
        const int rc = x % NSPL;
        const int bh = x / NSPL;
        const int b = bh / HEADS, h = bh % HEADS;

        if (x == 0) {    // zero G (768 float4)
            float4* Gz = (float4*)(g_Acc + G_OFF);
            #pragma unroll
            for (int i = 0; i < 4; i++)
                Gz[tid + 192 * i] = make_float4(0.f, 0.f, 0.f, 0.f);
        }

        // geometry (uniform): a(c) in {aMin,cut1}, bd(c) in {cut2,bMax}
        const int f0 = h << 16;
        const int f1 = f0 + 65536;
        int aMin = 1 << 30, cut1 = 0, cut2 = 1 << 30, bMax = 0;
        #pragma unroll
        for (int c = 0; c < 12; c++) {
            int na = f0 - 64 * c;
            int a  = (na <= 0) ? 0 : (na + 767) / 768;
            int bd = (f1 - 64 * c - 64) / 768 + 1;
            if (bd > SEQ) bd = SEQ;
            aMin = min(aMin, a); cut1 = max(cut1, a);
            cut2 = min(cut2, bd); bMax = max(bMax, bd);
        }

        const int L  = bMax - aMin;
        const int lo = aMin + (L * rc)      / NSPL;
        const int hi = aMin + (L * (rc + 1)) / NSPL;

        const float4* vp = (const float4*)(value + (size_t)b * SEQ * EMB) + tid;

        float4 P0 = make_float4(0.f,0.f,0.f,0.f), P1 = P0, P2 = P0;
        {   const int e = min(hi, cut1);
            for (int s = lo; s < e; s++) {
                float4 v = vp[(size_t)s * 192];
                P0.x += v.x; P0.y += v.y; P0.z += v.z; P0.w += v.w;
            }
        }
        {   const int st = max(lo, cut1), e = min(hi, cut2);
            #pragma unroll 4
            for (int s = st; s < e; s++) {
                float4 v = vp[(size_t)s * 192];
                P1.x += v.x; P1.y += v.y; P1.z += v.z; P1.w += v.w;
            }
        }
        {   const int st = max(lo, cut2);
            for (int s = st; s < hi; s++) {
                float4 v = vp[(size_t)s * 192];
                P2.x += v.x; P2.y += v.y; P2.z += v.z; P2.w += v.w;
            }
        }

        float4* R = (float4*)(g_Acc + (size_t)rc * RS_ONE) + (size_t)bh * HEADS * 192 + tid;
        #pragma unroll
        for (int c = 0; c < 12; c++) {
            int na = f0 - 64 * c;
            int a  = (na <= 0) ? 0 : (na + 767) / 768;
            int bd = (f1 - 64 * c - 64) / 768 + 1;
            if (bd > SEQ) bd = SEQ;

            float4 r = P1;
            if (a == aMin)  { r.x+=P0.x; r.y+=P0.y; r.z+=P0.z; r.w+=P0.w; }
            if (bd == bMax) { r.x+=P2.x; r.y+=P2.y; r.z+=P2.z; r.w+=P2.w; }
            R[c * 192] = r;
        }
    }

    grid_barrier();

    // ============================ PHASE 2: kgemm ===========================
    if (x < 144) {
        const int c  = x / 12;
        const int jt = x % 12;

        // Ws_t[k][d] = Wv[64c+d][64jt + k]
        for (int f = tid; f < 1024; f += 192) {
            int d = f >> 4, kq = f & 15;
            float4 v = *(const float4*)(Wv + (size_t)(64 * c + d) * EMB + jt * 64 + kq * 4);
            Ws_t[4*kq+0][d] = v.x; Ws_t[4*kq+1][d] = v.y;
            Ws_t[4*kq+2][d] = v.z; Ws_t[4*kq+3][d] = v.w;
        }
        // As_t[k][bh] = sum over replicas of RS[bh][c][64jt + k]
        for (int f = tid; f < 768; f += 192) {
            int bh = f >> 4, kq = f & 15;
            const size_t off = ((size_t)bh * HEADS + c) * 192 + jt * 16 + kq;
            float4 v = ((const float4*)g_Acc)[off];
            #pragma unroll
            for (int rc = 1; rc < NSPL; rc++) {
                float4 u = ((const float4*)(g_Acc + (size_t)rc * RS_ONE))[off];
                v.x += u.x; v.y += u.y; v.z += u.z; v.w += u.w;
            }
            As_t[4*kq+0][bh] = v.x; As_t[4*kq+1][bh] = v.y;
            As_t[4*kq+2][bh] = v.z; As_t[4*kq+3][bh] = v.w;
        }
        __syncthreads();

        const int tx = tid & 15;     // 4 d's
        const int ty = tid >> 4;     // 0..11 -> 4 bh's

        float acc[4][4] = {};
        #pragma unroll 8
        for (int k = 0; k < 64; k++) {
            float4 a4 = *(const float4*)&As_t[k][ty * 4];
            float4 b4 = *(const float4*)&Ws_t[k][tx * 4];
            const float a[4] = {a4.x, a4.y, a4.z, a4.w};
            const float bb[4] = {b4.x, b4.y, b4.z, b4.w};
            #pragma unroll
            for (int u = 0; u < 4; u++)
                #pragma unroll
                for (int v = 0; v < 4; v++)
                    acc[u][v] = fmaf(a[u], bb[v], acc[u][v]);
        }

        #pragma unroll
        for (int u = 0; u < 4; u++) {
            int bh = ty * 4 + u;
            int b = bh / HEADS, hh = bh % HEADS;
            float* gp = g_Acc + G_OFF + b * EMB + hh * HDIM + tx * 4;
            #pragma unroll
            for (int v = 0; v < 4; v++)
                atomicAdd(gp + v, acc[u][v]);
        }
    }

    grid_barrier();

    // =========================== PHASE 3: broadcast ========================
    {
        float4 Gv[4];
        #pragma unroll
        for (int b = 0; b < 4; b++)
            Gv[b] = ((const float4*)(g_Acc + G_OFF + b * EMB))[tid];

        #pragma unroll
        for (int i = 0; i < 15; i++) {
            int row = x + NBLK * i;
            if (row < BATCH * SEQ)
                ((float4*)(out + (size_t)row * EMB))[tid] = Gv[row >> 10];
        }
    }
}

// ---------------------------------------------------------------------------
extern "C" void kernel_launch(void* const* d_in, const int* in_sizes, int n_in,
                              void* d_out, int out_size)
{
    // metadata order: key, query, value, Wk, Wq, Wv
    const float* value = (const float*)d_in[2];
    const float* Wv    = (const float*)d_in[5];
    float* out = (float*)d_out;

    fused_kernel<<<NBLK, 192>>>(value, Wv, out);
}

// round 12
// speedup vs baseline: 1.0618x; 1.0618x over previous
#include <cuda_runtime.h>
#include <cstdint>

#define BATCH 4
#define SEQ   1024
#define EMB   768
#define HEADS 12
#define HDIM  64
#define BH    (BATCH*HEADS)    // 48
#define NSPL  12               // scan row-chunk replicas
#define SCAN_BLKS (BH * NSPL)  // 576

#define RS_ONE   (BH * HEADS * EMB)      // 442368 floats per replica
#define G_ELEMS  (BATCH * EMB)
#define G_OFF    (NSPL * RS_ONE)

// [0, NSPL*RS_ONE) = RS replicas (fully overwritten by scan every call)
// [G_OFF, +G_ELEMS) = G (zeroed by scan block 0, atomic-reduced by kgemm)
__device__ float g_Acc[NSPL * RS_ONE + G_ELEMS];

// ---------------------------------------------------------------------------
// K1: scan.  grid = 576: x = bh*12 + rc.  block = 192 thr = one full 768-float
// row as float4.  ~7 rows per block; three clamped monotone sub-loops
// (P0/P1/P2 around the <=2 uniform cuts); 12 direct STG.128 into replica rc.
// Single writer per RS bin -> no atomics, no smem.
// ---------------------------------------------------------------------------
__global__ void __launch_bounds__(192) scan_kernel(const float* __restrict__ value)
{
    const int x  = blockIdx.x;
    const int rc = x % NSPL;
    const int bh = x / NSPL;
    const int b = bh / HEADS, h = bh % HEADS;
    const int tid = threadIdx.x;

    if (x == 0) {    // zero G (768 float4)
        float4* Gz = (float4*)(g_Acc + G_OFF);
        #pragma unroll
        for (int i = 0; i < 4; i++)
            Gz[tid + 192 * i] = make_float4(0.f, 0.f, 0.f, 0.f);
    }

    // geometry (uniform): a(c) in {aMin,cut1}, bd(c) in {cut2,bMax}
    const int f0 = h << 16;
    const int f1 = f0 + 65536;
    int aMin = 1 << 30, cut1 = 0, cut2 = 1 << 30, bMax = 0;
    #pragma unroll
    for (int c = 0; c < 12; c++) {
        int na = f0 - 64 * c;
        int a  = (na <= 0) ? 0 : (na + 767) / 768;
        int bd = (f1 - 64 * c - 64) / 768 + 1;
        if (bd > SEQ) bd = SEQ;
        aMin = min(aMin, a); cut1 = max(cut1, a);
        cut2 = min(cut2, bd); bMax = max(bMax, bd);
    }

    const int L  = bMax - aMin;
    const int lo = aMin + (L * rc)      / NSPL;
    const int hi = aMin + (L * (rc + 1)) / NSPL;

    const float4* vp = (const float4*)(value + (size_t)b * SEQ * EMB) + tid;

    float4 P0 = make_float4(0.f,0.f,0.f,0.f), P1 = P0, P2 = P0;
    {   const int e = min(hi, cut1);
        for (int s = lo; s < e; s++) {
            float4 v = vp[(size_t)s * 192];
            P0.x += v.x; P0.y += v.y; P0.z += v.z; P0.w += v.w;
        }
    }
    {   const int st = max(lo, cut1), e = min(hi, cut2);
        #pragma unroll 4
        for (int s = st; s < e; s++) {
            float4 v = vp[(size_t)s * 192];
            P1.x += v.x; P1.y += v.y; P1.z += v.z; P1.w += v.w;
        }
    }
    {   const int st = max(lo, cut2);
        for (int s = st; s < hi; s++) {
            float4 v = vp[(size_t)s * 192];
            P2.x += v.x; P2.y += v.y; P2.z += v.z; P2.w += v.w;
        }
    }

    float4* R = (float4*)(g_Acc + (size_t)rc * RS_ONE) + (size_t)bh * HEADS * 192 + tid;
    #pragma unroll
    for (int c = 0; c < 12; c++) {
        int na = f0 - 64 * c;
        int a  = (na <= 0) ? 0 : (na + 767) / 768;
        int bd = (f1 - 64 * c - 64) / 768 + 1;
        if (bd > SEQ) bd = SEQ;

        float4 r = P1;
        if (a == aMin)  { r.x+=P0.x; r.y+=P0.y; r.z+=P0.z; r.w+=P0.w; }
        if (bd == bMax) { r.x+=P2.x; r.y+=P2.y; r.z+=P2.z; r.w+=P2.w; }
        R[c * 192] = r;
    }
}

// ---------------------------------------------------------------------------
// K2: K-split GEMM.  grid = 144 (c = blk/12, jt = blk%12), 192 threads.
// Transposed smem tiles -> 2x LDS.128 + 16 FFMA per k.
// As = sum of 12 RS replicas' slices; atomicAdd partials into G.
// ---------------------------------------------------------------------------
__global__ void __launch_bounds__(192) kgemm_kernel(const float* __restrict__ Wv)
{
    const int c  = blockIdx.x / 12;
    const int jt = blockIdx.x % 12;
    const int tid = threadIdx.x;

    __shared__ float As_t[64][52];   // [k][bh]
    __shared__ float Ws_t[64][68];   // [k][d]

    // Ws_t[k][d] = Wv[64c+d][64jt + k]
    for (int f = tid; f < 1024; f += 192) {
        int d = f >> 4, kq = f & 15;
        float4 v = *(const float4*)(Wv + (size_t)(64 * c + d) * EMB + jt * 64 + kq * 4);
        Ws_t[4*kq+0][d] = v.x; Ws_t[4*kq+1][d] = v.y;
        Ws_t[4*kq+2][d] = v.z; Ws_t[4*kq+3][d] = v.w;
    }
    // As_t[k][bh] = sum over replicas of RS[bh][c][64jt + k]
    for (int f = tid; f < 768; f += 192) {
        int bh = f >> 4, kq = f & 15;
        const size_t off = ((size_t)bh * HEADS + c) * 192 + jt * 16 + kq;
        float4 v = ((const float4*)g_Acc)[off];
        #pragma unroll
        for (int rc = 1; rc < NSPL; rc++) {
            float4 u = ((const float4*)(g_Acc + (size_t)rc * RS_ONE))[off];
            v.x += u.x; v.y += u.y; v.z += u.z; v.w += u.w;
        }
        As_t[4*kq+0][bh] = v.x; As_t[4*kq+1][bh] = v.y;
        As_t[4*kq+2][bh] = v.z; As_t[4*kq+3][bh] = v.w;
    }
    __syncthreads();

    const int tx = tid & 15;     // 4 d's
    const int ty = tid >> 4;     // 0..11 -> 4 bh's

    float acc[4][4] = {};
    #pragma unroll 8
    for (int k = 0; k < 64; k++) {
        float4 a4 = *(const float4*)&As_t[k][ty * 4];
        float4 b4 = *(const float4*)&Ws_t[k][tx * 4];
        const float a[4]  = {a4.x, a4.y, a4.z, a4.w};
        const float bb[4] = {b4.x, b4.y, b4.z, b4.w};
        #pragma unroll
        for (int u = 0; u < 4; u++)
            #pragma unroll
            for (int v = 0; v < 4; v++)
                acc[u][v] = fmaf(a[u], bb[v], acc[u][v]);
    }

    #pragma unroll
    for (int u = 0; u < 4; u++) {
        int bh = ty * 4 + u;
        int b = bh / HEADS, hh = bh % HEADS;
        float* gp = g_Acc + G_OFF + b * EMB + hh * HDIM + tx * 4;
        #pragma unroll
        for (int v = 0; v < 4; v++)
            atomicAdd(gp + v, acc[u][v]);
    }
}

// ---------------------------------------------------------------------------
// K3: out[b, q, :] = G[b, :].  1024 blocks x 192 threads, 4 rows per block.
// ---------------------------------------------------------------------------
__global__ void __launch_bounds__(192) broadcast_kernel(float* __restrict__ out)
{
    const int row0 = blockIdx.x * 4;           // 4 | 1024 -> single b per block
    const int b = row0 >> 10;
    const int c4 = threadIdx.x;

    const float4 v = ((const float4*)(g_Acc + G_OFF + b * EMB))[c4];
    float4* o = (float4*)(out + (size_t)row0 * EMB) + c4;
    #pragma unroll
    for (int i = 0; i < 4; i++)
        o[(size_t)i * 192] = v;
}

// ---------------------------------------------------------------------------
extern "C" void kernel_launch(void* const* d_in, const int* in_sizes, int n_in,
                              void* d_out, int out_size)
{
    // metadata order: key, query, value, Wk, Wq, Wv
    const float* value = (const float*)d_in[2];
    const float* Wv    = (const float*)d_in[5];
    float* out = (float*)d_out;

    scan_kernel<<<SCAN_BLKS, 192>>>(value);
    kgemm_kernel<<<144, 192>>>(Wv);
    broadcast_kernel<<<1024, 192>>>(out);
}

// round 13
// speedup vs baseline: 1.1641x; 1.0964x over previous
#include <cuda_runtime.h>
#include <cstdint>

#define BATCH 4
#define SEQ   1024
#define EMB   768
#define HEADS 12
#define HDIM  64
#define BH    (BATCH*HEADS)    // 48
#define NSPL  8                // scan row-chunk replicas
#define SCAN_BLKS (BH * NSPL)  // 384

#define RS_ONE   (BH * HEADS * EMB)      // 442368 floats per replica
#define G_ELEMS  (BATCH * EMB)
#define G_OFF    (NSPL * RS_ONE)

// [0, NSPL*RS_ONE) = RS replicas (fully overwritten by scan every call)
// [G_OFF, +G_ELEMS) = G (zeroed by scan block 0, atomic-reduced by kgemm)
__device__ float g_Acc[NSPL * RS_ONE + G_ELEMS];

// Precomputed geometry, h-indexed.  A(h,c) = ceil((1024h - c)/12); segment of
// (h,c) is rows [A(h,c), A(h+1,c)).  aMin/cut1 = min/max_c A(h,c);
// cut2/bMax = min/max_c A(h+1,c).  add0 bit c: A(h,c)==aMin (c gets P0);
// add2 bit c: A(h+1,c)==bMax (c gets P2).
__constant__ short c_aMin[12] = {0, 85,170,256,341,426,512,597,682,768,853,938};
__constant__ short c_cut1[12] = {0, 86,171,256,342,427,512,598,683,768,854,939};
__constant__ short c_cut2[12] = {85,170,256,341,426,512,597,682,768,853,938,1024};
__constant__ short c_bMax[12] = {86,171,256,342,427,512,598,683,768,854,939,1024};
__constant__ unsigned c_add0[12] = {0xFFF,0xFF0,0xF00,0xFFF,0xFF0,0xF00,
                                    0xFFF,0xFF0,0xF00,0xFFF,0xFF0,0xF00};
__constant__ unsigned c_add2[12] = {0x00F,0x0FF,0xFFF,0x00F,0x0FF,0xFFF,
                                    0x00F,0x0FF,0xFFF,0x00F,0x0FF,0xFFF};

// ---------------------------------------------------------------------------
// K1: scan.  grid = 384: x = bh*NSPL + rc.  block = 192 thr = one full
// 768-float row as float4.  ~10 rows per block; three clamped monotone
// sub-loops (P0/P1/P2 around the uniform cuts); 12 direct STG.128 into
// replica rc.  Single writer per RS bin -> no atomics, no smem, NO divisions.
// ---------------------------------------------------------------------------
__global__ void __launch_bounds__(192) scan_kernel(const float* __restrict__ value)
{
    const int x  = blockIdx.x;
    const int rc = x % NSPL;
    const int bh = x / NSPL;
    const int b = bh / HEADS, h = bh % HEADS;
    const int tid = threadIdx.x;

    if (x == 0) {    // zero G (768 float4)
        float4* Gz = (float4*)(g_Acc + G_OFF);
        #pragma unroll
        for (int i = 0; i < 4; i++)
            Gz[tid + 192 * i] = make_float4(0.f, 0.f, 0.f, 0.f);
    }

    const int aMin = c_aMin[h], cut1 = c_cut1[h];
    const int cut2 = c_cut2[h], bMax = c_bMax[h];
    const unsigned m0 = c_add0[h], m2 = c_add2[h];

    const int L  = bMax - aMin;
    const int lo = aMin + (L * rc)      / NSPL;
    const int hi = aMin + (L * (rc + 1)) / NSPL;

    const float4* vp = (const float4*)(value + (size_t)b * SEQ * EMB) + tid;

    float4 P0 = make_float4(0.f,0.f,0.f,0.f), P1 = P0, P2 = P0;
    {   const int e = min(hi, cut1);
        for (int s = lo; s < e; s++) {
            float4 v = vp[(size_t)s * 192];
            P0.x += v.x; P0.y += v.y; P0.z += v.z; P0.w += v.w;
        }
    }
    {   const int st = max(lo, cut1), e = min(hi, cut2);
        #pragma unroll 4
        for (int s = st; s < e; s++) {
            float4 v = vp[(size_t)s * 192];
            P1.x += v.x; P1.y += v.y; P1.z += v.z; P1.w += v.w;
        }
    }
    {   const int st = max(lo, cut2);
        for (int s = st; s < hi; s++) {
            float4 v = vp[(size_t)s * 192];
            P2.x += v.x; P2.y += v.y; P2.z += v.z; P2.w += v.w;
        }
    }

    float4* R = (float4*)(g_Acc + (size_t)rc * RS_ONE) + (size_t)bh * HEADS * 192 + tid;
    #pragma unroll
    for (int c = 0; c < 12; c++) {
        float4 r = P1;
        if ((m0 >> c) & 1) { r.x+=P0.x; r.y+=P0.y; r.z+=P0.z; r.w+=P0.w; }
        if ((m2 >> c) & 1) { r.x+=P2.x; r.y+=P2.y; r.z+=P2.z; r.w+=P2.w; }
        R[c * 192] = r;
    }
}

// ---------------------------------------------------------------------------
// K2: K-split GEMM.  grid = 144 (c = blk/12, jt = blk%12), 192 threads.
// Transposed smem tiles -> 2x LDS.128 + 16 FFMA per k.
// As = sum of NSPL RS replicas' slices; atomicAdd partials into G.
// ---------------------------------------------------------------------------
__global__ void __launch_bounds__(192) kgemm_kernel(const float* __restrict__ Wv)
{
    const int c  = blockIdx.x / 12;
    const int jt = blockIdx.x % 12;
    const int tid = threadIdx.x;

    __shared__ float As_t[64][52];   // [k][bh]
    __shared__ float Ws_t[64][68];   // [k][d]

    // Ws_t[k][d] = Wv[64c+d][64jt + k]
    for (int f = tid; f < 1024; f += 192) {
        int d = f >> 4, kq = f & 15;
        float4 v = *(const float4*)(Wv + (size_t)(64 * c + d) * EMB + jt * 64 + kq * 4);
        Ws_t[4*kq+0][d] = v.x; Ws_t[4*kq+1][d] = v.y;
        Ws_t[4*kq+2][d] = v.z; Ws_t[4*kq+3][d] = v.w;
    }
    // As_t[k][bh] = sum over replicas of RS[bh][c][64jt + k]
    for (int f = tid; f < 768; f += 192) {
        int bh = f >> 4, kq = f & 15;
        const size_t off = ((size_t)bh * HEADS + c) * 192 + jt * 16 + kq;
        float4 v = ((const float4*)g_Acc)[off];
        #pragma unroll
        for (int rc = 1; rc < NSPL; rc++) {
            float4 u = ((const float4*)(g_Acc + (size_t)rc * RS_ONE))[off];
            v.x += u.x; v.y += u.y; v.z += u.z; v.w += u.w;
        }
        As_t[4*kq+0][bh] = v.x; As_t[4*kq+1][bh] = v.y;
        As_t[4*kq+2][bh] = v.z; As_t[4*kq+3][bh] = v.w;
    }
    __syncthreads();

    const int tx = tid & 15;     // 4 d's
    const int ty = tid >> 4;     // 0..11 -> 4 bh's

    float acc[4][4] = {};
    #pragma unroll 8
    for (int k = 0; k < 64; k++) {
        float4 a4 = *(const float4*)&As_t[k][ty * 4];
        float4 b4 = *(const float4*)&Ws_t[k][tx * 4];
        const float a[4]  = {a4.x, a4.y, a4.z, a4.w};
        const float bb[4] = {b4.x, b4.y, b4.z, b4.w};
        #pragma unroll
        for (int u = 0; u < 4; u++)
            #pragma unroll
            for (int v = 0; v < 4; v++)
                acc[u][v] = fmaf(a[u], bb[v], acc[u][v]);
    }

    #pragma unroll
    for (int u = 0; u < 4; u++) {
        int bh = ty * 4 + u;
        int b = bh / HEADS, hh = bh % HEADS;
        float* gp = g_Acc + G_OFF + b * EMB + hh * HDIM + tx * 4;
        #pragma unroll
        for (int v = 0; v < 4; v++)
            atomicAdd(gp + v, acc[u][v]);
    }
}

// ---------------------------------------------------------------------------
// K3: out[b, q, :] = G[b, :].  1024 blocks x 192 threads, 4 rows per block.
// ---------------------------------------------------------------------------
__global__ void __launch_bounds__(192) broadcast_kernel(float* __restrict__ out)
{
    const int row0 = blockIdx.x * 4;           // 4 | 1024 -> single b per block
    const int b = row0 >> 10;
    const int c4 = threadIdx.x;

    const float4 v = ((const float4*)(g_Acc + G_OFF + b * EMB))[c4];
    float4* o = (float4*)(out + (size_t)row0 * EMB) + c4;
    #pragma unroll
    for (int i = 0; i < 4; i++)
        o[(size_t)i * 192] = v;
}

// ---------------------------------------------------------------------------
extern "C" void kernel_launch(void* const* d_in, const int* in_sizes, int n_in,
                              void* d_out, int out_size)
{
    // metadata order: key, query, value, Wk, Wq, Wv
    const float* value = (const float*)d_in[2];
    const float* Wv    = (const float*)d_in[5];
    float* out = (float*)d_out;

    scan_kernel<<<SCAN_BLKS, 192>>>(value);
    kgemm_kernel<<<144, 192>>>(Wv);
    broadcast_kernel<<<1024, 192>>>(out);
}